// round 17
// baseline (speedup 1.0000x reference)
#include <cuda_runtime.h>
#include <math.h>

// Problem constants (fixed by setup_inputs): N=16, T=2048, D=2
#define TT 2048
#define LOG2PI_F 1.8378770664093453f
#define LN2F     0.6931471805599453f

__device__ __forceinline__ float ex2f(float x) {
    float r;
    asm("ex2.approx.f32 %0, %1;" : "=f"(r) : "f"(x));
    return r;
}

// (x, x) packed
__device__ __forceinline__ unsigned long long dup2(float x) {
    unsigned long long d;
    asm("mov.b64 %0, {%1, %1};" : "=l"(d) : "f"(x));
    return d;
}

// (lo, hi) packed
__device__ __forceinline__ unsigned long long packf2(float lo, float hi) {
    unsigned long long d;
    asm("mov.b64 %0, {%1, %2};" : "=l"(d) : "f"(lo), "f"(hi));
    return d;
}

// u01 = xp * XS + (yp * YS + A); A/XS/YS are dup'd j-scalars, xp/yp are
// packed row-pair constants. Unpack to (u0, u1).
__device__ __forceinline__ void pair_u(unsigned long long A,
                                       unsigned long long XS,
                                       unsigned long long YS,
                                       unsigned long long xp,
                                       unsigned long long yp,
                                       float& u0, float& u1) {
    asm("{\n\t"
        ".reg .b64 t;\n\t"
        "fma.rn.f32x2 t, %3, %4, %2;\n\t"
        "fma.rn.f32x2 t, %5, %6, t;\n\t"
        "mov.b64 {%0, %1}, t;\n\t"
        "}"
        : "=f"(u0), "=f"(u1)
        : "l"(A), "l"(yp), "l"(YS), "l"(xp), "l"(XS));
}

// acc (packed pair) += (e0, e1)
__device__ __forceinline__ void acc2(unsigned long long& acc, float e0, float e1) {
    asm("{\n\t"
        ".reg .b64 p;\n\t"
        "mov.b64 p, {%1, %2};\n\t"
        "add.rn.f32x2 %0, %0, p;\n\t"
        "}"
        : "+l"(acc) : "f"(e0), "f"(e1));
}

__device__ __forceinline__ void unpack2(unsigned long long v, float& lo, float& hi) {
    asm("mov.b64 {%0, %1}, %2;" : "=f"(lo), "=f"(hi) : "l"(v));
}

// ---------------------------------------------------------------------------
// Fused kernel. Block = (batch n, slice k of 8), 512 threads (16 warps),
// 1 block/SM (grid 128).
// Phase 1: build SoA sA/sxs/sys + sE = 2^{c2}; in-place exclusive scan of sE.
// Phase 2 (TRANSPOSED): lane = j. Per pair s (tl = k+8s, th = 63-tl) the
//   63 j-groups (32 j each) of the concatenated pair stream go to warps
//   c=0..3 as 16/16/16/15 groups. Per group, the warp computes all 32 rows
//   of the owning tile in two 16-row passes; row constants (x_i,y_i) live
//   as packed f32x2 register pairs, j-data as dup'd pairs from ONE coalesced
//   LDS per array. Per-lane partials are transpose-reduced with a 5-stage
//   select+shfl butterfly (lane -> row). Tails (31 predicated j, scheme-A)
//   on warps c=3 (one per SMSP).
// Phase 3: sum 4 chunk partials per tile + epilogue.
// ---------------------------------------------------------------------------
__global__ void __launch_bounds__(512, 1)
fused_kernel(const float* __restrict__ tim,
             const float* __restrict__ loc,
             const float* __restrict__ mu0_p,
             const float* __restrict__ ls0_p,
             const float* __restrict__ cd_p,
             const float* __restrict__ sls_p,
             float* __restrict__ out) {
    const int b    = blockIdx.x;
    const int n    = b >> 3;               // batch
    const int k    = b & 7;                // slice
    const int tid  = threadIdx.x;
    const int wid  = tid >> 5;
    const int lane = tid & 31;
    const int s    = wid & 3;              // pair id == SMSP id
    const int c    = wid >> 2;             // chunk id 0..3

    __shared__ __align__(16) float sA [TT];   // 8KB  A_j
    __shared__ __align__(16) float sxs[TT];   // 8KB  2*h2l*x_j
    __shared__ __align__(16) float sys[TT];   // 8KB  2*h2l*y_j
    __shared__ float  sE[TT];                 // 8KB  E_j -> prefix P_j
    __shared__ float  wtot[16], wbase[16];
    __shared__ float  sacc[16][2][32];        // [warp][seg(tl/th)][row lane]

    const float cd  = *cd_p;
    const float sls = *sls_p;
    const float sp  = log1pf(__expf(cd));  // softplus(coeff_decay)
    const float rc2 = 1.0f / (sp * LN2F);
    const float h2l = 0.5f * __expf(-2.0f * sls) / LN2F;

    const float*  __restrict__ timn = tim + n * TT;
    const float2* __restrict__ locv = ((const float2*)loc) + n * TT;

    // ---- Phase 1a: build SoA pack + E ----
#pragma unroll
    for (int t = 0; t < TT / 512; t++) {
        const int j = t * 512 + tid;
        const float  tj = timn[j];
        const float2 xy = locv[j];
        const float c2 = tj * rc2;
        sA [j] = fmaf(-h2l, fmaf(xy.x, xy.x, xy.y * xy.y), c2);
        sxs[j] = 2.0f * h2l * xy.x;
        sys[j] = 2.0f * h2l * xy.y;
        sE [j] = ex2f(c2);
    }
    __syncthreads();

    // ---- Phase 1b: block scan (exclusive prefix of sE, in place) ----
    {
        const int base = tid << 2;
        float e0 = sE[base + 0], e1 = sE[base + 1];
        float e2 = sE[base + 2], e3 = sE[base + 3];
        const float part = (e0 + e1) + (e2 + e3);

        float inc = part;
#pragma unroll
        for (int o = 1; o < 32; o <<= 1) {
            float v = __shfl_up_sync(0xffffffffu, inc, o);
            if (lane >= o) inc += v;
        }
        if (lane == 31) wtot[wid] = inc;
        __syncthreads();
        if (tid < 16) {
            float v = wtot[tid], s2 = v;
#pragma unroll
            for (int o = 1; o < 16; o <<= 1) {
                float u = __shfl_up_sync(0x0000ffffu, s2, o);
                if (tid >= o) s2 += u;
            }
            wbase[tid] = s2 - v;
        }
        __syncthreads();

        float run = wbase[wid] + (inc - part);
        sE[base + 0] = run; run += e0;
        sE[base + 1] = run; run += e1;
        sE[base + 2] = run; run += e2;
        sE[base + 3] = run;
    }
    __syncthreads();

    // ---- Phase 2: transposed dense work ----
    const int tl = k + (s << 3);           // 0..31
    const int th = 63 - tl;                // 32..63
    const int ga = c << 4;                 // group range [ga, gb) of 63
    const int gb = (ga + 16 < 63) ? ga + 16 : 63;

#pragma unroll 1
    for (int seg = 0; seg < 2; seg++) {
        const int t  = seg ? th : tl;
        const int g0 = seg ? (ga > tl ? ga : tl) : ga;
        const int g1 = seg ? gb : (gb < tl ? gb : tl);
        const int goff = seg ? tl : 0;     // group -> local group

        float Sv = 0.0f;
        if (g0 < g1) {
            float sres[32];
#pragma unroll
            for (int pass = 0; pass < 2; pass++) {
                // packed row constants for rows (t*32 + 16*pass + 0..15)
                unsigned long long xp[8], yp[8];
#pragma unroll
                for (int ip = 0; ip < 8; ip++) {
                    const int i0 = (t << 5) + (pass << 4) + (ip << 1);
                    const float2 l0 = locv[i0];
                    const float2 l1 = locv[i0 + 1];
                    xp[ip] = packf2(l0.x, l1.x);
                    yp[ip] = packf2(l0.y, l1.y);
                }
                unsigned long long acc[8];
#pragma unroll
                for (int ip = 0; ip < 8; ip++) acc[ip] = 0ULL;

                for (int g = g0; g < g1; g++) {
                    const int jb = ((g - goff) << 5) + lane;
                    const unsigned long long A2  = dup2(sA [jb]);
                    const unsigned long long XS2 = dup2(sxs[jb]);
                    const unsigned long long YS2 = dup2(sys[jb]);
#pragma unroll
                    for (int ip = 0; ip < 8; ip++) {
                        float u0, u1;
                        pair_u(A2, XS2, YS2, xp[ip], yp[ip], u0, u1);
                        acc2(acc[ip], ex2f(u0), ex2f(u1));
                    }
                }
#pragma unroll
                for (int ip = 0; ip < 8; ip++) {
                    float lo, hi;
                    unpack2(acc[ip], lo, hi);
                    sres[(pass << 4) + (ip << 1) + 0] = lo;
                    sres[(pass << 4) + (ip << 1) + 1] = hi;
                }
            }

            // 5-stage transpose-reduce: lane ends with sum for row = lane
            float v16[16];
#pragma unroll
            for (int m = 0; m < 16; m++) {
                float a = sres[2 * m], bq = sres[2 * m + 1];
                float send = (lane & 1) ? a : bq;
                float recv = __shfl_xor_sync(0xffffffffu, send, 1);
                float keep = (lane & 1) ? bq : a;
                v16[m] = keep + recv;
            }
            float v8[8];
#pragma unroll
            for (int m = 0; m < 8; m++) {
                float a = v16[2 * m], bq = v16[2 * m + 1];
                float send = (lane & 2) ? a : bq;
                float recv = __shfl_xor_sync(0xffffffffu, send, 2);
                float keep = (lane & 2) ? bq : a;
                v8[m] = keep + recv;
            }
            float v4[4];
#pragma unroll
            for (int m = 0; m < 4; m++) {
                float a = v8[2 * m], bq = v8[2 * m + 1];
                float send = (lane & 4) ? a : bq;
                float recv = __shfl_xor_sync(0xffffffffu, send, 4);
                float keep = (lane & 4) ? bq : a;
                v4[m] = keep + recv;
            }
            float v2[2];
#pragma unroll
            for (int m = 0; m < 2; m++) {
                float a = v4[2 * m], bq = v4[2 * m + 1];
                float send = (lane & 8) ? a : bq;
                float recv = __shfl_xor_sync(0xffffffffu, send, 8);
                float keep = (lane & 8) ? bq : a;
                v2[m] = keep + recv;
            }
            {
                float a = v2[0], bq = v2[1];
                float send = (lane & 16) ? a : bq;
                float recv = __shfl_xor_sync(0xffffffffu, send, 16);
                float keep = (lane & 16) ? bq : a;
                Sv = keep + recv;
            }
        }

        // Tails on c==3: seg0 -> tile tl's tail, seg1 -> tile th's tail.
        // Scheme-A: lane = row; j = 32t + jt, include iff jt < lane.
        if (c == 3) {
            const int tb = t << 5;
            const float2 xyt = locv[tb + lane];
            float st = 0.0f;
#pragma unroll
            for (int jt = 0; jt < 31; jt++) {
                float u = fmaf(xyt.x, sxs[tb + jt],
                          fmaf(xyt.y, sys[tb + jt], sA[tb + jt]));
                float e = ex2f(u);
                st += (jt < lane) ? e : 0.0f;
            }
            Sv += st;
        }

        sacc[wid][seg][lane] = Sv;
    }
    __syncthreads();

    // ---- Phase 3: reduction + epilogue (warps 0..7 -> 8 tiles) ----
    if (wid < 8) {
        const bool low = (wid < 4);
        const int  ss  = wid & 3;
        const int  t_o = low ? (k + (ss << 3)) : (63 - (k + (ss << 3)));
        const int  sg  = low ? 0 : 1;
        const int  i   = (t_o << 5) + lane;
        const float2 xyo = locv[(t_o << 5) + lane];

        float S = 0.0f;
#pragma unroll
        for (int cc = 0; cc < 4; cc++)
            S += sacc[(cc << 2) | ss][sg][lane];

        float res;
        if (i == 0) {
            const float mu0 = *mu0_p;
            const float ls0 = *ls0_p;
            const float iv  = __expf(-2.0f * ls0);
            const float dx = xyo.x - mu0, dy = xyo.y - mu0;
            res = -0.5f * iv * fmaf(dx, dx, dy * dy) - 2.0f * ls0 - LOG2PI_F;
        } else {
            const float B2 = -h2l * fmaf(xyo.x, xyo.x, xyo.y * xyo.y);
            const float K  = 2.0f * sls + LOG2PI_F;
            res = __logf(S) + LN2F * B2 - K - __logf(sE[i]);
        }
        out[n * TT + i] = res;
    }
}

// ---------------------------------------------------------------------------
extern "C" void kernel_launch(void* const* d_in, const int* in_sizes, int n_in,
                              void* d_out, int out_size) {
    const float* tim  = (const float*)d_in[0];  // (N, T, 1)
    const float* loc  = (const float*)d_in[1];  // (N, T, 2)
    const float* mu0  = (const float*)d_in[2];
    const float* ls0  = (const float*)d_in[3];
    const float* cd   = (const float*)d_in[4];
    const float* sls  = (const float*)d_in[5];
    float* out = (float*)d_out;

    const int N = in_sizes[0] / TT;             // 16

    fused_kernel<<<N * 8, 512>>>(tim, loc, mu0, ls0, cd, sls, out);
}